// round 12
// baseline (speedup 1.0000x reference)
#include <cuda_runtime.h>
#include <math.h>

#define T_STEPS 1000
#define BATCH   1024
#define IN_DIM  80
#define HID     128
#define OUT_DIM 10

__device__ float g_coef[T_STEPS];
__device__ float g_wrp[HID * HID];      // permuted w_rec^T (R2 layout)
__device__ float g_winp[IN_DIM * HID];  // permuted w_in

// ---------------------------------------------------------------------------
// Prep: coefficients (closed form c_u = 0.9^(T-u) - 0.8^(T-u)) and permuted
// weights:
//   g_wrp [k*128 + ln*4 + r] = w_rec[(r*32+ln)*128 + k]   (k = 0..127)
//   g_winp[k*128 + ln*4 + r] = w_in [(r*32+ln)* 80 + k]   (k = 0..79)
// so a lane fetches its 4 h-values {r=0..3} for column k as one float4.
// ---------------------------------------------------------------------------
__global__ void prep_kernel(const float* __restrict__ wrec,
                            const float* __restrict__ win) {
    int idx = blockIdx.x * blockDim.x + threadIdx.x;
    if (idx < HID * HID) {
        int k = idx >> 7, j = idx & 127;
        int ln = j >> 2, r = j & 3;
        g_wrp[idx] = wrec[(r * 32 + ln) * HID + k];
    }
    if (idx < IN_DIM * HID) {
        int k = idx >> 7, j = idx & 127;
        int ln = j >> 2, r = j & 3;
        g_winp[idx] = win[(r * 32 + ln) * IN_DIM + k];
    }
    if (idx < T_STEPS) {
        double n = (double)(T_STEPS - idx);
        g_coef[idx] = (float)(pow(0.9, n) - pow(0.8, n));
    }
}

// ---------------------------------------------------------------------------
// FUSED kernel: one warp per batch element, all 1000 steps, input GEMM
// computed inline per step (fills the LDS-latency stall slots of the
// recurrent drain with FFMA work; g_xw eliminated entirely).
//
// Per step:
//   A[h]  = sum_{k=0..79 ascending} x[t,b,k] * w_in[h,k]   (fmaf chain from 0)
//   LIF update (R2's exact op forms/order)
//   R[h]  = sum_{spiking k ascending} w_rec[h,k]           (separate acc)
//   i     = (i_dec + A) + R
// h = r*32 + lane, r = 0..3. All fp ops bitwise identical to the R2/R3 path.
// ---------------------------------------------------------------------------
#define SIM_SMEM ((HID * HID + IN_DIM * HID + T_STEPS + OUT_DIM * HID) * 4)

__global__ __launch_bounds__(256)
void sim_kernel(const float* __restrict__ x, const float* __restrict__ wout,
                float* __restrict__ out) {
    extern __shared__ float sm[];
    float* wrp  = sm;                      // [16384]
    float* winp = wrp + HID * HID;         // [10240]
    float* cf   = winp + IN_DIM * HID;     // [1000]
    float* wo   = cf + T_STEPS;            // [10][128]
    int tid = threadIdx.x, lane = tid & 31, wid = tid >> 5;
    int b = blockIdx.x * 8 + wid;

    {
        const float4* s4 = (const float4*)g_wrp;
        float4* d4 = (float4*)wrp;
        for (int e = tid; e < HID * HID / 4; e += 256) d4[e] = s4[e];
        const float4* s4b = (const float4*)g_winp;
        float4* d4b = (float4*)winp;
        for (int e = tid; e < IN_DIM * HID / 4; e += 256) d4b[e] = s4b[e];
    }
    for (int e = tid; e < T_STEPS; e += 256) cf[e] = g_coef[e];
    for (int e = tid; e < OUT_DIM * HID; e += 256) wo[e] = wout[e];
    __syncthreads();

    float v0 = 0.f, v1 = 0.f, v2 = 0.f, v3 = 0.f;
    float i0 = 0.f, i1 = 0.f, i2 = 0.f, i3 = 0.f;
    float a0 = 0.f, a1 = 0.f, a2 = 0.f, a3 = 0.f;

    const float* xp = x + (size_t)b * IN_DIM + lane;   // x[t][b][lane + ...]
    const size_t xstride = (size_t)BATCH * IN_DIM;
    const float4* wr4  = (const float4*)wrp;    // rec col k: wr4 [k*32 + lane]
    const float4* win4 = (const float4*)winp;   // in  col k: win4[k*32 + lane]

    // prefetch x row for t = 0 (xr2 valid for lane < 16: k = 64..79)
    float xn0 = xp[0], xn1 = xp[32], xn2 = (lane < 16) ? xp[64] : 0.f;

    for (int t = 0; t < T_STEPS; ++t) {
        float xc0 = xn0, xc1 = xn1, xc2 = xn2;
        if (t + 1 < T_STEPS) {
            const float* p = xp + (size_t)(t + 1) * xstride;
            xn0 = p[0]; xn1 = p[32]; xn2 = (lane < 16) ? p[64] : 0.f;
        }
        float ct = cf[t];

        // ---- inline input GEMM: A = x[t,b,:] @ w_in[h,:], ascending k ----
        float A0 = 0.f, A1 = 0.f, A2 = 0.f, A3 = 0.f;
#pragma unroll
        for (int k = 0; k < IN_DIM; ++k) {
            float xv = __shfl_sync(0xffffffffu,
                                   (k < 32) ? xc0 : (k < 64) ? xc1 : xc2,
                                   k & 31);
            float4 wq = win4[k * 32 + lane];
            A0 = fmaf(xv, wq.x, A0);
            A1 = fmaf(xv, wq.y, A1);
            A2 = fmaf(xv, wq.z, A2);
            A3 = fmaf(xv, wq.w, A3);
        }

        // ---- LIF update (R2's exact forms/order) ----
        float vd0 = __fadd_rn(v0, __fmul_rn(0.1f, __fadd_rn(__fsub_rn(0.f, v0), i0)));
        float vd1 = __fadd_rn(v1, __fmul_rn(0.1f, __fadd_rn(__fsub_rn(0.f, v1), i1)));
        float vd2 = __fadd_rn(v2, __fmul_rn(0.1f, __fadd_rn(__fsub_rn(0.f, v2), i2)));
        float vd3 = __fadd_rn(v3, __fmul_rn(0.1f, __fadd_rn(__fsub_rn(0.f, v3), i3)));
        float id0 = __fsub_rn(i0, __fmul_rn(0.2f, i0));
        float id1 = __fsub_rn(i1, __fmul_rn(0.2f, i1));
        float id2 = __fsub_rn(i2, __fmul_rn(0.2f, i2));
        float id3 = __fsub_rn(i3, __fmul_rn(0.2f, i3));
        bool z0 = __fsub_rn(vd0, 1.0f) > 0.0f;
        bool z1 = __fsub_rn(vd1, 1.0f) > 0.0f;
        bool z2 = __fsub_rn(vd2, 1.0f) > 0.0f;
        bool z3 = __fsub_rn(vd3, 1.0f) > 0.0f;
        v0 = z0 ? 0.0f : vd0;
        v1 = z1 ? 0.0f : vd1;
        v2 = z2 ? 0.0f : vd2;
        v3 = z3 ? 0.0f : vd3;
        if (z0) a0 = __fadd_rn(a0, ct);
        if (z1) a1 = __fadd_rn(a1, ct);
        if (z2) a2 = __fadd_rn(a2, ct);
        if (z3) a3 = __fadd_rn(a3, ct);

        // ---- recurrent sparse drain, ascending k, separate accumulators ----
        unsigned m0 = __ballot_sync(0xffffffffu, z0);
        unsigned m1 = __ballot_sync(0xffffffffu, z1);
        unsigned m2 = __ballot_sync(0xffffffffu, z2);
        unsigned m3 = __ballot_sync(0xffffffffu, z3);
        float R0 = 0.f, R1 = 0.f, R2 = 0.f, R3 = 0.f;
        while (m0) {
            int k = __ffs((int)m0) - 1; m0 &= m0 - 1;
            float4 q = wr4[k * 32 + lane];
            R0 = __fadd_rn(R0, q.x); R1 = __fadd_rn(R1, q.y);
            R2 = __fadd_rn(R2, q.z); R3 = __fadd_rn(R3, q.w);
        }
        while (m1) {
            int k = 32 + __ffs((int)m1) - 1; m1 &= m1 - 1;
            float4 q = wr4[k * 32 + lane];
            R0 = __fadd_rn(R0, q.x); R1 = __fadd_rn(R1, q.y);
            R2 = __fadd_rn(R2, q.z); R3 = __fadd_rn(R3, q.w);
        }
        while (m2) {
            int k = 64 + __ffs((int)m2) - 1; m2 &= m2 - 1;
            float4 q = wr4[k * 32 + lane];
            R0 = __fadd_rn(R0, q.x); R1 = __fadd_rn(R1, q.y);
            R2 = __fadd_rn(R2, q.z); R3 = __fadd_rn(R3, q.w);
        }
        while (m3) {
            int k = 96 + __ffs((int)m3) - 1; m3 &= m3 - 1;
            float4 q = wr4[k * 32 + lane];
            R0 = __fadd_rn(R0, q.x); R1 = __fadd_rn(R1, q.y);
            R2 = __fadd_rn(R2, q.z); R3 = __fadd_rn(R3, q.w);
        }

        // i_new = (i_dec + A) + R   (reference association)
        i0 = __fadd_rn(__fadd_rn(id0, A0), R0);
        i1 = __fadd_rn(__fadd_rn(id1, A1), R1);
        i2 = __fadd_rn(__fadd_rn(id2, A2), R2);
        i3 = __fadd_rn(__fadd_rn(id3, A3), R3);
    }

    // Readout: vo[o] = sum_h acc[h]*w_out[o][h]; h = r*32+lane
    float vo[OUT_DIM];
#pragma unroll
    for (int o = 0; o < OUT_DIM; ++o) {
        const float* wp = &wo[o * HID];
        float p = a0 * wp[lane] + a1 * wp[32 + lane] + a2 * wp[64 + lane] +
                  a3 * wp[96 + lane];
#pragma unroll
        for (int s = 16; s; s >>= 1) p += __shfl_xor_sync(0xffffffffu, p, s);
        vo[o] = p;
    }
    if (lane == 0) {
        float mx = vo[0];
#pragma unroll
        for (int o = 1; o < OUT_DIM; ++o) mx = fmaxf(mx, vo[o]);
        float se = 0.f;
#pragma unroll
        for (int o = 0; o < OUT_DIM; ++o) se += expf(vo[o] - mx);
        float lse = mx + logf(se);
#pragma unroll
        for (int o = 0; o < OUT_DIM; ++o) out[b * OUT_DIM + o] = vo[o] - lse;
    }
}

extern "C" void kernel_launch(void* const* d_in, const int* in_sizes, int n_in,
                              void* d_out, int out_size) {
    const float* x     = (const float*)d_in[0];
    const float* w_in  = (const float*)d_in[1];
    const float* w_rec = (const float*)d_in[2];
    const float* w_out = (const float*)d_in[3];
    float* out = (float*)d_out;

    cudaFuncSetAttribute(sim_kernel, cudaFuncAttributeMaxDynamicSharedMemorySize,
                         SIM_SMEM);

    prep_kernel<<<64, 256>>>(w_rec, w_in);
    sim_kernel<<<BATCH / 8, 256, SIM_SMEM>>>(x, w_out, out);
}

// round 14
// speedup vs baseline: 1.4341x; 1.4341x over previous
#include <cuda_runtime.h>
#include <math.h>

#define T_STEPS 1000
#define BATCH   1024
#define IN_DIM  80
#define HID     128
#define OUT_DIM 10

__device__ float g_xw[(size_t)T_STEPS * BATCH * HID];   // 524 MB (BSS)
__device__ float g_coef[T_STEPS];
__device__ float g_wrp[HID * HID];   // R2-layout permuted w_rec^T

// ---------------------------------------------------------------------------
// Prep: coefficients (closed form c_u = 0.9^(T-u) - 0.8^(T-u)) and permuted
// recurrent weights: g_wrp[k*128 + ln*4 + r] = wrec[(r*32+ln)*128 + k].
// ---------------------------------------------------------------------------
__global__ void prep_kernel(const float* __restrict__ wrec) {
    int idx = blockIdx.x * blockDim.x + threadIdx.x;
    if (idx < HID * HID) {
        int k = idx >> 7, j = idx & 127;
        int ln = j >> 2, r = j & 3;
        g_wrp[idx] = wrec[(r * 32 + ln) * HID + k];
    }
    if (idx < T_STEPS) {
        double n = (double)(T_STEPS - idx);
        g_coef[idx] = (float)(pow(0.9, n) - pow(0.8, n));
    }
}

// ---------------------------------------------------------------------------
// Input GEMM: (T*B,80)@(80,128) -> g_xw. 512 threads/CTA, 8x4 microtile:
//   mrow = (tid>>5)*8  (warp-uniform -> a-reads are broadcasts)
//   mcol = tid&31, cols mcol+32j (stride-84 float4 reads tile banks 0..31)
// Per-element chain: fmaf ascending k (quads k..k+3) — bitwise == R2/R8.
// 16 warps/SM (1 CTA/SM via 86KB smem + ~90 regs) to cover LDS latency.
// ---------------------------------------------------------------------------
#define XS_STR 84
#define WS_STR 84
#define GEMM_SMEM ((128 * XS_STR + 128 * WS_STR) * 4)   // 86,016 B

__global__ __launch_bounds__(512, 1)
void gemm_in(const float* __restrict__ x, const float* __restrict__ w) {
    extern __shared__ float sm[];
    float* xs = sm;                 // [128][XS_STR]
    float* ws = sm + 128 * XS_STR;  // [128][WS_STR]
    int tid = threadIdx.x;
    size_t rowbase = (size_t)blockIdx.x * 128;

    const float4* xg = (const float4*)(x + rowbase * IN_DIM);
#pragma unroll
    for (int it = 0; it < 5; ++it) {
        int e = tid + it * 512;         // 2560 float4 total
        int row = e / 20, c4 = e % 20;
        float4 v = xg[e];
        *(float4*)&xs[row * XS_STR + c4 * 4] = v;
    }
    for (int e = tid; e < HID * IN_DIM; e += 512)
        ws[(e / IN_DIM) * WS_STR + (e % IN_DIM)] = w[e];
    __syncthreads();

    int mrow = (tid >> 5) * 8;   // warp-uniform
    int mcol = tid & 31;
    float acc[8][4];
#pragma unroll
    for (int i = 0; i < 8; i++)
#pragma unroll
        for (int j = 0; j < 4; j++) acc[i][j] = 0.f;

#pragma unroll 2
    for (int k = 0; k < IN_DIM; k += 4) {
        float4 a4[8], b4[4];
#pragma unroll
        for (int i = 0; i < 8; i++)
            a4[i] = *(const float4*)&xs[(mrow + i) * XS_STR + k];
#pragma unroll
        for (int j = 0; j < 4; j++)
            b4[j] = *(const float4*)&ws[(mcol + 32 * j) * WS_STR + k];
#pragma unroll
        for (int i = 0; i < 8; i++)
#pragma unroll
            for (int j = 0; j < 4; j++) {
                acc[i][j] = fmaf(a4[i].x, b4[j].x, acc[i][j]);
                acc[i][j] = fmaf(a4[i].y, b4[j].y, acc[i][j]);
                acc[i][j] = fmaf(a4[i].z, b4[j].z, acc[i][j]);
                acc[i][j] = fmaf(a4[i].w, b4[j].w, acc[i][j]);
            }
    }

    float* op = g_xw + rowbase * HID;
#pragma unroll
    for (int i = 0; i < 8; i++)
#pragma unroll
        for (int j = 0; j < 4; j++)
            op[(mrow + i) * HID + mcol + 32 * j] = acc[i][j];
}

// ---------------------------------------------------------------------------
// Simulation: R2's exact numeric path (1 warp/element, h=r*32+lane, ballot
// drain ascending-k, separate R, (i_dec+A)+R association). Changes vs R2:
//   - xw prefetch depth 2 (same loads, issued earlier; covers DRAM latency)
//   - drain adds as packed add.rn.f32x2 (independent IEEE halves — bitwise
//     identical per-accumulator chains, validated R5)
// ---------------------------------------------------------------------------
#define SIM_SMEM ((HID * HID + T_STEPS + OUT_DIM * HID) * 4)

__global__ __launch_bounds__(256)
void sim_kernel(const float* __restrict__ wout, float* __restrict__ out) {
    extern __shared__ float sm[];
    float* wrp = sm;                 // [16384]
    float* cf  = wrp + HID * HID;    // [1000]
    float* wo  = cf + T_STEPS;       // [10][128]
    int tid = threadIdx.x, lane = tid & 31, wid = tid >> 5;
    int b = blockIdx.x * 8 + wid;

    {
        const float4* s4 = (const float4*)g_wrp;
        float4* d4 = (float4*)wrp;
        for (int e = tid; e < HID * HID / 4; e += 256) d4[e] = s4[e];
    }
    for (int e = tid; e < T_STEPS; e += 256) cf[e] = g_coef[e];
    for (int e = tid; e < OUT_DIM * HID; e += 256) wo[e] = wout[e];
    __syncthreads();

    float v0 = 0.f, v1 = 0.f, v2 = 0.f, v3 = 0.f;
    float i0 = 0.f, i1 = 0.f, i2 = 0.f, i3 = 0.f;
    float a0 = 0.f, a1 = 0.f, a2 = 0.f, a3 = 0.f;

    const float* xwp = g_xw + (size_t)b * HID + lane;
    const size_t tstride = (size_t)BATCH * HID;
    const float4* wr4 = (const float4*)wrp;   // column k: wr4[k*32 + lane]

    // prefetch depth 2
    float xA0 = xwp[0], xA1 = xwp[32], xA2 = xwp[64], xA3 = xwp[96];
    const float* p1 = xwp + tstride;
    float xB0 = p1[0], xB1 = p1[32], xB2 = p1[64], xB3 = p1[96];

    for (int t = 0; t < T_STEPS; ++t) {
        float xc0 = xA0, xc1 = xA1, xc2 = xA2, xc3 = xA3;
        xA0 = xB0; xA1 = xB1; xA2 = xB2; xA3 = xB3;
        if (t + 2 < T_STEPS) {
            const float* p = xwp + (size_t)(t + 2) * tstride;
            xB0 = p[0]; xB1 = p[32]; xB2 = p[64]; xB3 = p[96];
        }
        float ct = cf[t];

        float vd0 = __fadd_rn(v0, __fmul_rn(0.1f, __fadd_rn(__fsub_rn(0.f, v0), i0)));
        float vd1 = __fadd_rn(v1, __fmul_rn(0.1f, __fadd_rn(__fsub_rn(0.f, v1), i1)));
        float vd2 = __fadd_rn(v2, __fmul_rn(0.1f, __fadd_rn(__fsub_rn(0.f, v2), i2)));
        float vd3 = __fadd_rn(v3, __fmul_rn(0.1f, __fadd_rn(__fsub_rn(0.f, v3), i3)));
        float id0 = __fsub_rn(i0, __fmul_rn(0.2f, i0));
        float id1 = __fsub_rn(i1, __fmul_rn(0.2f, i1));
        float id2 = __fsub_rn(i2, __fmul_rn(0.2f, i2));
        float id3 = __fsub_rn(i3, __fmul_rn(0.2f, i3));
        bool z0 = __fsub_rn(vd0, 1.0f) > 0.0f;
        bool z1 = __fsub_rn(vd1, 1.0f) > 0.0f;
        bool z2 = __fsub_rn(vd2, 1.0f) > 0.0f;
        bool z3 = __fsub_rn(vd3, 1.0f) > 0.0f;
        v0 = z0 ? 0.0f : vd0;
        v1 = z1 ? 0.0f : vd1;
        v2 = z2 ? 0.0f : vd2;
        v3 = z3 ? 0.0f : vd3;
        if (z0) a0 = __fadd_rn(a0, ct);
        if (z1) a1 = __fadd_rn(a1, ct);
        if (z2) a2 = __fadd_rn(a2, ct);
        if (z3) a3 = __fadd_rn(a3, ct);

        unsigned m0 = __ballot_sync(0xffffffffu, z0);
        unsigned m1 = __ballot_sync(0xffffffffu, z1);
        unsigned m2 = __ballot_sync(0xffffffffu, z2);
        unsigned m3 = __ballot_sync(0xffffffffu, z3);
        // Rp01 = {R0,R1}, Rp23 = {R2,R3}: packed zero-init (+0.0f,+0.0f);
        // each half is an independent fp32 add chain in the exact R2 order.
        unsigned long long Rp01 = 0ull, Rp23 = 0ull;
        while (m0) {
            int k = __ffs((int)m0) - 1; m0 &= m0 - 1;
            const unsigned long long* q =
                (const unsigned long long*)&wr4[k * 32 + lane];
            asm("add.rn.f32x2 %0, %0, %1;" : "+l"(Rp01) : "l"(q[0]));
            asm("add.rn.f32x2 %0, %0, %1;" : "+l"(Rp23) : "l"(q[1]));
        }
        while (m1) {
            int k = 32 + __ffs((int)m1) - 1; m1 &= m1 - 1;
            const unsigned long long* q =
                (const unsigned long long*)&wr4[k * 32 + lane];
            asm("add.rn.f32x2 %0, %0, %1;" : "+l"(Rp01) : "l"(q[0]));
            asm("add.rn.f32x2 %0, %0, %1;" : "+l"(Rp23) : "l"(q[1]));
        }
        while (m2) {
            int k = 64 + __ffs((int)m2) - 1; m2 &= m2 - 1;
            const unsigned long long* q =
                (const unsigned long long*)&wr4[k * 32 + lane];
            asm("add.rn.f32x2 %0, %0, %1;" : "+l"(Rp01) : "l"(q[0]));
            asm("add.rn.f32x2 %0, %0, %1;" : "+l"(Rp23) : "l"(q[1]));
        }
        while (m3) {
            int k = 96 + __ffs((int)m3) - 1; m3 &= m3 - 1;
            const unsigned long long* q =
                (const unsigned long long*)&wr4[k * 32 + lane];
            asm("add.rn.f32x2 %0, %0, %1;" : "+l"(Rp01) : "l"(q[0]));
            asm("add.rn.f32x2 %0, %0, %1;" : "+l"(Rp23) : "l"(q[1]));
        }
        float R0, R1, R2, R3;
        asm("mov.b64 {%0, %1}, %2;" : "=f"(R0), "=f"(R1) : "l"(Rp01));
        asm("mov.b64 {%0, %1}, %2;" : "=f"(R2), "=f"(R3) : "l"(Rp23));

        i0 = __fadd_rn(__fadd_rn(id0, xc0), R0);
        i1 = __fadd_rn(__fadd_rn(id1, xc1), R1);
        i2 = __fadd_rn(__fadd_rn(id2, xc2), R2);
        i3 = __fadd_rn(__fadd_rn(id3, xc3), R3);
    }

    float vo[OUT_DIM];
#pragma unroll
    for (int o = 0; o < OUT_DIM; ++o) {
        const float* wp = &wo[o * HID];
        float p = a0 * wp[lane] + a1 * wp[32 + lane] + a2 * wp[64 + lane] +
                  a3 * wp[96 + lane];
#pragma unroll
        for (int s = 16; s; s >>= 1) p += __shfl_xor_sync(0xffffffffu, p, s);
        vo[o] = p;
    }
    if (lane == 0) {
        float mx = vo[0];
#pragma unroll
        for (int o = 1; o < OUT_DIM; ++o) mx = fmaxf(mx, vo[o]);
        float se = 0.f;
#pragma unroll
        for (int o = 0; o < OUT_DIM; ++o) se += expf(vo[o] - mx);
        float lse = mx + logf(se);
#pragma unroll
        for (int o = 0; o < OUT_DIM; ++o) out[b * OUT_DIM + o] = vo[o] - lse;
    }
}

extern "C" void kernel_launch(void* const* d_in, const int* in_sizes, int n_in,
                              void* d_out, int out_size) {
    const float* x     = (const float*)d_in[0];
    const float* w_in  = (const float*)d_in[1];
    const float* w_rec = (const float*)d_in[2];
    const float* w_out = (const float*)d_in[3];
    float* out = (float*)d_out;

    cudaFuncSetAttribute(gemm_in, cudaFuncAttributeMaxDynamicSharedMemorySize,
                         GEMM_SMEM);
    cudaFuncSetAttribute(sim_kernel, cudaFuncAttributeMaxDynamicSharedMemorySize,
                         SIM_SMEM);

    prep_kernel<<<64, 256>>>(w_rec);
    gemm_in<<<(T_STEPS * BATCH) / 128, 512, GEMM_SMEM>>>(x, w_in);
    sim_kernel<<<BATCH / 8, 256, SIM_SMEM>>>(w_out, out);
}